// round 5
// baseline (speedup 1.0000x reference)
#include <cuda_runtime.h>
#include <cuda_bf16.h>

#define BATCH 1024
#define SEQ   512
#define HID   64
#define GATES 256
#define NR    8
#define NCTA  (BATCH / NR)   // 128
#define NTHR  256            // 8 warps = 4 k-groups x 2 cell-half warps

typedef unsigned long long ull;

struct __align__(16) Smem {
    // Weight layout: W[k][col], col = j*4 + hq (cell j, gate hq: 0=i,1=f,2=g,3=o)
    // -> lane owning cell j reads its 4 gates with one conflict-free LDS.128
    float W1[HID][GATES];          //  64 KB (W_hh1)
    float W2[2 * HID][GATES];      // 128 KB ([W_ih2 ; W_hh2])
    float hb[2 * HID][NR];         //   4 KB [k][row]; k<64: h1, k>=64: h2 (single buffer)
    ulonglong2 pexA[4][3][64];     //  12 KB [pair][slot][cell] gates (i,f)
    ulonglong2 pexB[4][3][64];     //  12 KB gates (g,o)
    float wih1v[GATES];
    float b1v[GATES];
    float b2v[GATES];
    float wlin[HID];
    float xs[2][NR];
    float outp[4][2][2];           // [pair][hh][e]
    float blin;
};   // ~228.7 KB total (fits 232448-B opt-in limit)

__device__ __forceinline__ ull pk2(float lo, float hi) {
    ull r; asm("mov.b64 %0, {%1, %2};" : "=l"(r) : "f"(lo), "f"(hi)); return r;
}
__device__ __forceinline__ void unpk(ull v, float& lo, float& hi) {
    asm("mov.b64 {%0, %1}, %2;" : "=f"(lo), "=f"(hi) : "l"(v));
}
__device__ __forceinline__ void fma2(ull& d, ull a, ull b) {
    asm("fma.rn.f32x2 %0, %1, %2, %0;" : "+l"(d) : "l"(a), "l"(b));
}
__device__ __forceinline__ ull add2(ull a, ull b) {
    ull d; asm("add.rn.f32x2 %0, %1, %2;" : "=l"(d) : "l"(a), "l"(b)); return d;
}

__device__ __forceinline__ float sigf(float v) {
    float e = __expf(-v);
    return __fdividef(1.0f, 1.0f + e);
}
__device__ __forceinline__ float tanhf_(float v) {
    float e = __expf(2.0f * v);
    return 1.0f - __fdividef(2.0f, 1.0f + e);
}

// 8 k-steps: acc[q][p] += h[k][rows 2p,2p+1] * w[k][cell*4+q]
__device__ __forceinline__ void gemm8(const float* __restrict__ wp,
                                      const float* __restrict__ hp,
                                      ull acc[4][4]) {
#pragma unroll
    for (int kk = 0; kk < 8; kk++) {
        float4 wv = *reinterpret_cast<const float4*>(wp + kk * GATES);
        ulonglong2 hA = *reinterpret_cast<const ulonglong2*>(hp + kk * 8);      // rows {0,1},{2,3}
        ulonglong2 hB = *reinterpret_cast<const ulonglong2*>(hp + kk * 8 + 4);  // rows {4,5},{6,7}
        ull w;
        w = pk2(wv.x, wv.x);
        fma2(acc[0][0], hA.x, w); fma2(acc[0][1], hA.y, w);
        fma2(acc[0][2], hB.x, w); fma2(acc[0][3], hB.y, w);
        w = pk2(wv.y, wv.y);
        fma2(acc[1][0], hA.x, w); fma2(acc[1][1], hA.y, w);
        fma2(acc[1][2], hB.x, w); fma2(acc[1][3], hB.y, w);
        w = pk2(wv.z, wv.z);
        fma2(acc[2][0], hA.x, w); fma2(acc[2][1], hA.y, w);
        fma2(acc[2][2], hB.x, w); fma2(acc[2][3], hB.y, w);
        w = pk2(wv.w, wv.w);
        fma2(acc[3][0], hA.x, w); fma2(acc[3][1], hA.y, w);
        fma2(acc[3][2], hB.x, w); fma2(acc[3][3], hB.y, w);
    }
}

__global__ void __launch_bounds__(NTHR, 1)
lstm_persistent_kernel(const float* __restrict__ x,
                       const float* __restrict__ Wih1, const float* __restrict__ Whh1,
                       const float* __restrict__ bih1, const float* __restrict__ bhh1,
                       const float* __restrict__ Wih2, const float* __restrict__ Whh2,
                       const float* __restrict__ bih2, const float* __restrict__ bhh2,
                       const float* __restrict__ Wlin, const float* __restrict__ blin,
                       float* __restrict__ out) {
    extern __shared__ char smem_raw[];
    Smem& sm = *reinterpret_cast<Smem*>(smem_raw);

    const int tid  = threadIdx.x;
    const int wid  = tid >> 5;
    const int lane = tid & 31;
    const int row0 = blockIdx.x * NR;

    // ---- one-time staging ----
    for (int i = tid; i < GATES * HID; i += NTHR) {
        int gsrc = i >> 6, k = i & 63;
        int col = (gsrc & 63) * 4 + (gsrc >> 6);    // j*4 + hq
        sm.W1[k][col]      = Whh1[i];
        sm.W2[k][col]      = Wih2[i];
        sm.W2[64 + k][col] = Whh2[i];
    }
    for (int gsrc = tid; gsrc < GATES; gsrc += NTHR) {
        int col = (gsrc & 63) * 4 + (gsrc >> 6);
        sm.wih1v[col] = Wih1[gsrc];
        sm.b1v[col]   = bih1[gsrc] + bhh1[gsrc];
        sm.b2v[col]   = bih2[gsrc] + bhh2[gsrc];
    }
    if (tid < HID) sm.wlin[tid] = Wlin[tid];
    if (tid == 0)  sm.blin = blin[0];
    for (int i = tid; i < 2 * HID * NR; i += NTHR)
        reinterpret_cast<float*>(sm.hb)[i] = 0.0f;
    if (tid < NR) sm.xs[0][tid] = x[(row0 + tid) * SEQ + 0];
    __syncthreads();

    const int g   = wid >> 1;            // k-group / owned row-pair (rows 2g,2g+1)
    const int hh  = wid & 1;             // cell half
    const int j   = hh * 32 + lane;      // owned cell
    const int c4  = j * 4;               // column of this cell's 4 gates

    float c1a = 0.f, c1b = 0.f;          // c1 for rows 2g,2g+1 of cell j
    float c2a = 0.f, c2b = 0.f;

    const float wl = sm.wlin[j];

    for (int t = 0; t < SEQ; t++) {
        const int cur = t & 1, nxt = cur ^ 1;

        // finalize out[t-1] (outp written before last sync of prev step)
        if (t > 0 && tid < NR) {
            int g2 = tid >> 1, e = tid & 1;
            out[(row0 + tid) * SEQ + (t - 1)] =
                sm.blin + sm.outp[g2][0][e] + sm.outp[g2][1][e];
        }

        // ===== layer 1: acc = bias1 + x*wih1 + W_hh1 h1(t-1), K split 4x16 =====
        ull acc[4][4];
        if (g == 0) {
            float4 wiv = *reinterpret_cast<const float4*>(&sm.wih1v[c4]);
            float4 bv  = *reinterpret_cast<const float4*>(&sm.b1v[c4]);
            const float* xp = sm.xs[cur];
            ulonglong2 xA = *reinterpret_cast<const ulonglong2*>(xp);
            ulonglong2 xB = *reinterpret_cast<const ulonglong2*>(xp + 4);
            ull w, b;
            b = pk2(bv.x, bv.x); acc[0][0]=b; acc[0][1]=b; acc[0][2]=b; acc[0][3]=b;
            b = pk2(bv.y, bv.y); acc[1][0]=b; acc[1][1]=b; acc[1][2]=b; acc[1][3]=b;
            b = pk2(bv.z, bv.z); acc[2][0]=b; acc[2][1]=b; acc[2][2]=b; acc[2][3]=b;
            b = pk2(bv.w, bv.w); acc[3][0]=b; acc[3][1]=b; acc[3][2]=b; acc[3][3]=b;
            w = pk2(wiv.x, wiv.x);
            fma2(acc[0][0], xA.x, w); fma2(acc[0][1], xA.y, w);
            fma2(acc[0][2], xB.x, w); fma2(acc[0][3], xB.y, w);
            w = pk2(wiv.y, wiv.y);
            fma2(acc[1][0], xA.x, w); fma2(acc[1][1], xA.y, w);
            fma2(acc[1][2], xB.x, w); fma2(acc[1][3], xB.y, w);
            w = pk2(wiv.z, wiv.z);
            fma2(acc[2][0], xA.x, w); fma2(acc[2][1], xA.y, w);
            fma2(acc[2][2], xB.x, w); fma2(acc[2][3], xB.y, w);
            w = pk2(wiv.w, wiv.w);
            fma2(acc[3][0], xA.x, w); fma2(acc[3][1], xA.y, w);
            fma2(acc[3][2], xB.x, w); fma2(acc[3][3], xB.y, w);
        } else {
#pragma unroll
            for (int q = 0; q < 4; q++)
#pragma unroll
                for (int p = 0; p < 4; p++) acc[q][p] = 0ull;
        }
        {
            const float* wp = &sm.W1[g * 16][c4];
            const float* hp = &sm.hb[g * 16][0];
            gemm8(wp, hp, acc);
            gemm8(wp + 8 * GATES, hp + 8 * NR, acc);
        }
        // ship partials for row-pairs we don't own (compact slot = g - (g>p))
#pragma unroll
        for (int p = 0; p < 4; p++)
            if (p != g) {
                int s = (g < p) ? g : g - 1;
                sm.pexA[p][s][j] = make_ulonglong2(acc[0][p], acc[1][p]);
                sm.pexB[p][s][j] = make_ulonglong2(acc[2][p], acc[3][p]);
            }
        __syncthreads();

        // ===== reduce + activation 1 (rows 2g,2g+1 of cell j) =====
        {
            ull ai = acc[0][g], af = acc[1][g], ag = acc[2][g], ao = acc[3][g];
#pragma unroll
            for (int s = 0; s < 3; s++) {
                ulonglong2 ra = sm.pexA[g][s][j];
                ulonglong2 rb = sm.pexB[g][s][j];
                ai = add2(ai, ra.x); af = add2(af, ra.y);
                ag = add2(ag, rb.x); ao = add2(ao, rb.y);
            }
            float gi0, gi1, gf0, gf1, gg0, gg1, go0, go1;
            unpk(ai, gi0, gi1); unpk(af, gf0, gf1);
            unpk(ag, gg0, gg1); unpk(ao, go0, go1);
            float c0 = sigf(gf0) * c1a + sigf(gi0) * tanhf_(gg0);
            float c1 = sigf(gf1) * c1b + sigf(gi1) * tanhf_(gg1);
            c1a = c0; c1b = c1;
            float h0 = sigf(go0) * tanhf_(c0);
            float h1 = sigf(go1) * tanhf_(c1);
            *reinterpret_cast<ull*>(&sm.hb[j][2 * g]) = pk2(h0, h1);
        }
        __syncthreads();

        // ===== layer 2: acc = bias2 + W_ih2 h1(t) + W_hh2 h2(t-1), K split 4x32 =====
        if (g == 0) {
            float4 bv = *reinterpret_cast<const float4*>(&sm.b2v[c4]);
            ull b;
            b = pk2(bv.x, bv.x); acc[0][0]=b; acc[0][1]=b; acc[0][2]=b; acc[0][3]=b;
            b = pk2(bv.y, bv.y); acc[1][0]=b; acc[1][1]=b; acc[1][2]=b; acc[1][3]=b;
            b = pk2(bv.z, bv.z); acc[2][0]=b; acc[2][1]=b; acc[2][2]=b; acc[2][3]=b;
            b = pk2(bv.w, bv.w); acc[3][0]=b; acc[3][1]=b; acc[3][2]=b; acc[3][3]=b;
        } else {
#pragma unroll
            for (int q = 0; q < 4; q++)
#pragma unroll
                for (int p = 0; p < 4; p++) acc[q][p] = 0ull;
        }
        {
            // k range [g*32, g*32+32): g<2 hits h1 (new), g>=2 hits h2 (old)
            const float* wp = &sm.W2[g * 32][c4];
            const float* hp = &sm.hb[g * 32][0];
            gemm8(wp, hp, acc);
            gemm8(wp +  8 * GATES, hp +  8 * NR, acc);
            gemm8(wp + 16 * GATES, hp + 16 * NR, acc);
            gemm8(wp + 24 * GATES, hp + 24 * NR, acc);
        }
#pragma unroll
        for (int p = 0; p < 4; p++)
            if (p != g) {
                int s = (g < p) ? g : g - 1;
                sm.pexA[p][s][j] = make_ulonglong2(acc[0][p], acc[1][p]);
                sm.pexB[p][s][j] = make_ulonglong2(acc[2][p], acc[3][p]);
            }
        __syncthreads();

        // ===== reduce + activation 2 + output partial =====
        {
            ull ai = acc[0][g], af = acc[1][g], ag = acc[2][g], ao = acc[3][g];
#pragma unroll
            for (int s = 0; s < 3; s++) {
                ulonglong2 ra = sm.pexA[g][s][j];
                ulonglong2 rb = sm.pexB[g][s][j];
                ai = add2(ai, ra.x); af = add2(af, ra.y);
                ag = add2(ag, rb.x); ao = add2(ao, rb.y);
            }
            float gi0, gi1, gf0, gf1, gg0, gg1, go0, go1;
            unpk(ai, gi0, gi1); unpk(af, gf0, gf1);
            unpk(ag, gg0, gg1); unpk(ao, go0, go1);
            float c0 = sigf(gf0) * c2a + sigf(gi0) * tanhf_(gg0);
            float c1 = sigf(gf1) * c2b + sigf(gi1) * tanhf_(gg1);
            c2a = c0; c2b = c1;
            float h0 = sigf(go0) * tanhf_(c0);
            float h1 = sigf(go1) * tanhf_(c1);
            *reinterpret_cast<ull*>(&sm.hb[64 + j][2 * g]) = pk2(h0, h1);

            // output partial: sum over this warp's 32 cells
            float p0 = wl * h0, p1 = wl * h1;
#pragma unroll
            for (int off = 16; off > 0; off >>= 1) {
                p0 += __shfl_xor_sync(0xffffffffu, p0, off);
                p1 += __shfl_xor_sync(0xffffffffu, p1, off);
            }
            if (lane == 0) {
                sm.outp[g][hh][0] = p0;
                sm.outp[g][hh][1] = p1;
            }
        }
        if (tid < NR && (t + 1) < SEQ)
            sm.xs[nxt][tid] = x[(row0 + tid) * SEQ + t + 1];
        __syncthreads();
    }

    if (tid < NR) {
        int g2 = tid >> 1, e = tid & 1;
        out[(row0 + tid) * SEQ + (SEQ - 1)] =
            sm.blin + sm.outp[g2][0][e] + sm.outp[g2][1][e];
    }
}

extern "C" void kernel_launch(void* const* d_in, const int* in_sizes, int n_in,
                              void* d_out, int out_size) {
    const float* x     = (const float*)d_in[0];
    const float* Wih1  = (const float*)d_in[1];
    const float* Whh1  = (const float*)d_in[2];
    const float* bih1  = (const float*)d_in[3];
    const float* bhh1  = (const float*)d_in[4];
    const float* Wih2  = (const float*)d_in[5];
    const float* Whh2  = (const float*)d_in[6];
    const float* bih2  = (const float*)d_in[7];
    const float* bhh2  = (const float*)d_in[8];
    const float* Wlin  = (const float*)d_in[9];
    const float* blin  = (const float*)d_in[10];
    float* out = (float*)d_out;

    (void)in_sizes; (void)n_in; (void)out_size;

    static_assert(sizeof(Smem) <= 232448, "smem over sm_103a opt-in limit");
    cudaFuncSetAttribute(lstm_persistent_kernel,
                         cudaFuncAttributeMaxDynamicSharedMemorySize,
                         (int)sizeof(Smem));
    lstm_persistent_kernel<<<NCTA, NTHR, sizeof(Smem)>>>(
        x, Wih1, Whh1, bih1, bhh1, Wih2, Whh2, bih2, bhh2, Wlin, blin, out);
}

// round 6
// speedup vs baseline: 1.3994x; 1.3994x over previous
#include <cuda_runtime.h>
#include <cuda_bf16.h>

#define BATCH 1024
#define SEQ   512
#define HID   64
#define GATES 256
#define NR    8
#define NCTA  (BATCH / NR)   // 128
#define NTHR  256            // 8 warps = 4 k-groups x 2 cell-half warps

typedef unsigned long long ull;

struct __align__(16) Smem {
    // Weight layout: W[k][col], col = j*4 + hq (cell j, gate hq: 0=i,1=f,2=g,3=o)
    // -> lane owning cell j reads its 4 gates with one conflict-free LDS.128
    float W1[HID][GATES];          //  64 KB (W_hh1)
    float W2[2 * HID][GATES];      // 128 KB ([W_ih2 ; W_hh2])
    float hb[2 * HID][NR];         //   4 KB [k][row]; k<64: h1, k>=64: h2 (single buffer)
    ulonglong2 pexA[4][3][64];     //  12 KB [pair][slot][cell] gates (i,f)
    ulonglong2 pexB[4][3][64];     //  12 KB gates (g,o)
    float wih1v[GATES];
    float b1v[GATES];
    float b2v[GATES];
    float wlin[HID];
    float xs[2][NR];
    float outp[4][2][2];           // [pair][hh][e]
    float blin;
};   // ~228.7 KB total (fits 232448-B opt-in limit)

__device__ __forceinline__ ull pk2(float lo, float hi) {
    ull r; asm("mov.b64 %0, {%1, %2};" : "=l"(r) : "f"(lo), "f"(hi)); return r;
}
__device__ __forceinline__ void unpk(ull v, float& lo, float& hi) {
    asm("mov.b64 {%0, %1}, %2;" : "=f"(lo), "=f"(hi) : "l"(v));
}
__device__ __forceinline__ void fma2(ull& d, ull a, ull b) {
    asm("fma.rn.f32x2 %0, %1, %2, %0;" : "+l"(d) : "l"(a), "l"(b));
}
__device__ __forceinline__ ull add2(ull a, ull b) {
    ull d; asm("add.rn.f32x2 %0, %1, %2;" : "=l"(d) : "l"(a), "l"(b)); return d;
}

__device__ __forceinline__ float sigf(float v) {
    float e = __expf(-v);
    return __fdividef(1.0f, 1.0f + e);
}
__device__ __forceinline__ float tanhf_(float v) {
    float e = __expf(2.0f * v);
    return 1.0f - __fdividef(2.0f, 1.0f + e);
}

// 8 k-steps: acc[q][p] += h[k][rows 2p,2p+1] * w[k][cell*4+q]
__device__ __forceinline__ void gemm8(const float* __restrict__ wp,
                                      const float* __restrict__ hp,
                                      ull acc[4][4]) {
#pragma unroll
    for (int kk = 0; kk < 8; kk++) {
        float4 wv = *reinterpret_cast<const float4*>(wp + kk * GATES);
        ulonglong2 hA = *reinterpret_cast<const ulonglong2*>(hp + kk * 8);      // rows {0,1},{2,3}
        ulonglong2 hB = *reinterpret_cast<const ulonglong2*>(hp + kk * 8 + 4);  // rows {4,5},{6,7}
        ull w;
        w = pk2(wv.x, wv.x);
        fma2(acc[0][0], hA.x, w); fma2(acc[0][1], hA.y, w);
        fma2(acc[0][2], hB.x, w); fma2(acc[0][3], hB.y, w);
        w = pk2(wv.y, wv.y);
        fma2(acc[1][0], hA.x, w); fma2(acc[1][1], hA.y, w);
        fma2(acc[1][2], hB.x, w); fma2(acc[1][3], hB.y, w);
        w = pk2(wv.z, wv.z);
        fma2(acc[2][0], hA.x, w); fma2(acc[2][1], hA.y, w);
        fma2(acc[2][2], hB.x, w); fma2(acc[2][3], hB.y, w);
        w = pk2(wv.w, wv.w);
        fma2(acc[3][0], hA.x, w); fma2(acc[3][1], hA.y, w);
        fma2(acc[3][2], hB.x, w); fma2(acc[3][3], hB.y, w);
    }
}

// Extract this group's row-pair with STATIC indices only (no dynamic register
// array indexing -> no local-memory demotion).
__device__ __forceinline__ void own_pair(const ull acc[4][4], int g,
                                         ull& ai, ull& af, ull& ag, ull& ao) {
    ai = 0; af = 0; ag = 0; ao = 0;
#pragma unroll
    for (int p = 0; p < 4; p++)
        if (p == g) { ai = acc[0][p]; af = acc[1][p]; ag = acc[2][p]; ao = acc[3][p]; }
}

__global__ void __launch_bounds__(NTHR, 1)
lstm_persistent_kernel(const float* __restrict__ x,
                       const float* __restrict__ Wih1, const float* __restrict__ Whh1,
                       const float* __restrict__ bih1, const float* __restrict__ bhh1,
                       const float* __restrict__ Wih2, const float* __restrict__ Whh2,
                       const float* __restrict__ bih2, const float* __restrict__ bhh2,
                       const float* __restrict__ Wlin, const float* __restrict__ blin,
                       float* __restrict__ out) {
    extern __shared__ char smem_raw[];
    Smem& sm = *reinterpret_cast<Smem*>(smem_raw);

    const int tid  = threadIdx.x;
    const int wid  = tid >> 5;
    const int lane = tid & 31;
    const int row0 = blockIdx.x * NR;

    // ---- one-time staging ----
    for (int i = tid; i < GATES * HID; i += NTHR) {
        int gsrc = i >> 6, k = i & 63;
        int col = (gsrc & 63) * 4 + (gsrc >> 6);    // j*4 + hq
        sm.W1[k][col]      = Whh1[i];
        sm.W2[k][col]      = Wih2[i];
        sm.W2[64 + k][col] = Whh2[i];
    }
    for (int gsrc = tid; gsrc < GATES; gsrc += NTHR) {
        int col = (gsrc & 63) * 4 + (gsrc >> 6);
        sm.wih1v[col] = Wih1[gsrc];
        sm.b1v[col]   = bih1[gsrc] + bhh1[gsrc];
        sm.b2v[col]   = bih2[gsrc] + bhh2[gsrc];
    }
    if (tid < HID) sm.wlin[tid] = Wlin[tid];
    if (tid == 0)  sm.blin = blin[0];
    for (int i = tid; i < 2 * HID * NR; i += NTHR)
        reinterpret_cast<float*>(sm.hb)[i] = 0.0f;
    if (tid < NR) sm.xs[0][tid] = x[(row0 + tid) * SEQ + 0];
    __syncthreads();

    const int g   = wid >> 1;            // k-group / owned row-pair (rows 2g,2g+1)
    const int hh  = wid & 1;             // cell half
    const int j   = hh * 32 + lane;      // owned cell
    const int c4  = j * 4;               // column of this cell's 4 gates

    float c1a = 0.f, c1b = 0.f;          // c1 for rows 2g,2g+1 of cell j
    float c2a = 0.f, c2b = 0.f;

    const float wl = sm.wlin[j];

    for (int t = 0; t < SEQ; t++) {
        const int cur = t & 1, nxt = cur ^ 1;

        // finalize out[t-1] (outp written before last sync of prev step)
        if (t > 0 && tid < NR) {
            int g2 = tid >> 1, e = tid & 1;
            out[(row0 + tid) * SEQ + (t - 1)] =
                sm.blin + sm.outp[g2][0][e] + sm.outp[g2][1][e];
        }

        // ===== layer 1: acc = bias1 + x*wih1 + W_hh1 h1(t-1), K split 4x16 =====
        ull acc[4][4];
        if (g == 0) {
            float4 wiv = *reinterpret_cast<const float4*>(&sm.wih1v[c4]);
            float4 bv  = *reinterpret_cast<const float4*>(&sm.b1v[c4]);
            const float* xp = sm.xs[cur];
            ulonglong2 xA = *reinterpret_cast<const ulonglong2*>(xp);
            ulonglong2 xB = *reinterpret_cast<const ulonglong2*>(xp + 4);
            ull w, b;
            b = pk2(bv.x, bv.x); acc[0][0]=b; acc[0][1]=b; acc[0][2]=b; acc[0][3]=b;
            b = pk2(bv.y, bv.y); acc[1][0]=b; acc[1][1]=b; acc[1][2]=b; acc[1][3]=b;
            b = pk2(bv.z, bv.z); acc[2][0]=b; acc[2][1]=b; acc[2][2]=b; acc[2][3]=b;
            b = pk2(bv.w, bv.w); acc[3][0]=b; acc[3][1]=b; acc[3][2]=b; acc[3][3]=b;
            w = pk2(wiv.x, wiv.x);
            fma2(acc[0][0], xA.x, w); fma2(acc[0][1], xA.y, w);
            fma2(acc[0][2], xB.x, w); fma2(acc[0][3], xB.y, w);
            w = pk2(wiv.y, wiv.y);
            fma2(acc[1][0], xA.x, w); fma2(acc[1][1], xA.y, w);
            fma2(acc[1][2], xB.x, w); fma2(acc[1][3], xB.y, w);
            w = pk2(wiv.z, wiv.z);
            fma2(acc[2][0], xA.x, w); fma2(acc[2][1], xA.y, w);
            fma2(acc[2][2], xB.x, w); fma2(acc[2][3], xB.y, w);
            w = pk2(wiv.w, wiv.w);
            fma2(acc[3][0], xA.x, w); fma2(acc[3][1], xA.y, w);
            fma2(acc[3][2], xB.x, w); fma2(acc[3][3], xB.y, w);
        } else {
#pragma unroll
            for (int q = 0; q < 4; q++)
#pragma unroll
                for (int p = 0; p < 4; p++) acc[q][p] = 0ull;
        }
        {
            const float* wp = &sm.W1[g * 16][c4];
            const float* hp = &sm.hb[g * 16][0];
            gemm8(wp, hp, acc);
            gemm8(wp + 8 * GATES, hp + 8 * NR, acc);
        }
        // ship partials for row-pairs we don't own (compact slot = g - (g>p))
#pragma unroll
        for (int p = 0; p < 4; p++)
            if (p != g) {
                int s = (g < p) ? g : g - 1;
                sm.pexA[p][s][j] = make_ulonglong2(acc[0][p], acc[1][p]);
                sm.pexB[p][s][j] = make_ulonglong2(acc[2][p], acc[3][p]);
            }
        __syncthreads();

        // ===== reduce + activation 1 (rows 2g,2g+1 of cell j) =====
        {
            ull ai, af, ag, ao;
            own_pair(acc, g, ai, af, ag, ao);
#pragma unroll
            for (int s = 0; s < 3; s++) {
                ulonglong2 ra = sm.pexA[g][s][j];
                ulonglong2 rb = sm.pexB[g][s][j];
                ai = add2(ai, ra.x); af = add2(af, ra.y);
                ag = add2(ag, rb.x); ao = add2(ao, rb.y);
            }
            float gi0, gi1, gf0, gf1, gg0, gg1, go0, go1;
            unpk(ai, gi0, gi1); unpk(af, gf0, gf1);
            unpk(ag, gg0, gg1); unpk(ao, go0, go1);
            float c0 = sigf(gf0) * c1a + sigf(gi0) * tanhf_(gg0);
            float c1 = sigf(gf1) * c1b + sigf(gi1) * tanhf_(gg1);
            c1a = c0; c1b = c1;
            float h0 = sigf(go0) * tanhf_(c0);
            float h1 = sigf(go1) * tanhf_(c1);
            *reinterpret_cast<ull*>(&sm.hb[j][2 * g]) = pk2(h0, h1);
        }
        __syncthreads();

        // ===== layer 2: acc = bias2 + W_ih2 h1(t) + W_hh2 h2(t-1), K split 4x32 =====
        if (g == 0) {
            float4 bv = *reinterpret_cast<const float4*>(&sm.b2v[c4]);
            ull b;
            b = pk2(bv.x, bv.x); acc[0][0]=b; acc[0][1]=b; acc[0][2]=b; acc[0][3]=b;
            b = pk2(bv.y, bv.y); acc[1][0]=b; acc[1][1]=b; acc[1][2]=b; acc[1][3]=b;
            b = pk2(bv.z, bv.z); acc[2][0]=b; acc[2][1]=b; acc[2][2]=b; acc[2][3]=b;
            b = pk2(bv.w, bv.w); acc[3][0]=b; acc[3][1]=b; acc[3][2]=b; acc[3][3]=b;
        } else {
#pragma unroll
            for (int q = 0; q < 4; q++)
#pragma unroll
                for (int p = 0; p < 4; p++) acc[q][p] = 0ull;
        }
        {
            // k range [g*32, g*32+32): g<2 hits h1 (new), g>=2 hits h2 (old)
            const float* wp = &sm.W2[g * 32][c4];
            const float* hp = &sm.hb[g * 32][0];
            gemm8(wp, hp, acc);
            gemm8(wp +  8 * GATES, hp +  8 * NR, acc);
            gemm8(wp + 16 * GATES, hp + 16 * NR, acc);
            gemm8(wp + 24 * GATES, hp + 24 * NR, acc);
        }
#pragma unroll
        for (int p = 0; p < 4; p++)
            if (p != g) {
                int s = (g < p) ? g : g - 1;
                sm.pexA[p][s][j] = make_ulonglong2(acc[0][p], acc[1][p]);
                sm.pexB[p][s][j] = make_ulonglong2(acc[2][p], acc[3][p]);
            }
        __syncthreads();

        // ===== reduce + activation 2 + output partial =====
        {
            ull ai, af, ag, ao;
            own_pair(acc, g, ai, af, ag, ao);
#pragma unroll
            for (int s = 0; s < 3; s++) {
                ulonglong2 ra = sm.pexA[g][s][j];
                ulonglong2 rb = sm.pexB[g][s][j];
                ai = add2(ai, ra.x); af = add2(af, ra.y);
                ag = add2(ag, rb.x); ao = add2(ao, rb.y);
            }
            float gi0, gi1, gf0, gf1, gg0, gg1, go0, go1;
            unpk(ai, gi0, gi1); unpk(af, gf0, gf1);
            unpk(ag, gg0, gg1); unpk(ao, go0, go1);
            float c0 = sigf(gf0) * c2a + sigf(gi0) * tanhf_(gg0);
            float c1 = sigf(gf1) * c2b + sigf(gi1) * tanhf_(gg1);
            c2a = c0; c2b = c1;
            float h0 = sigf(go0) * tanhf_(c0);
            float h1 = sigf(go1) * tanhf_(c1);
            *reinterpret_cast<ull*>(&sm.hb[64 + j][2 * g]) = pk2(h0, h1);

            // output partial: sum over this warp's 32 cells
            float p0 = wl * h0, p1 = wl * h1;
#pragma unroll
            for (int off = 16; off > 0; off >>= 1) {
                p0 += __shfl_xor_sync(0xffffffffu, p0, off);
                p1 += __shfl_xor_sync(0xffffffffu, p1, off);
            }
            if (lane == 0) {
                sm.outp[g][hh][0] = p0;
                sm.outp[g][hh][1] = p1;
            }
        }
        if (tid < NR && (t + 1) < SEQ)
            sm.xs[nxt][tid] = x[(row0 + tid) * SEQ + t + 1];
        __syncthreads();
    }

    if (tid < NR) {
        int g2 = tid >> 1, e = tid & 1;
        out[(row0 + tid) * SEQ + (SEQ - 1)] =
            sm.blin + sm.outp[g2][0][e] + sm.outp[g2][1][e];
    }
}

extern "C" void kernel_launch(void* const* d_in, const int* in_sizes, int n_in,
                              void* d_out, int out_size) {
    const float* x     = (const float*)d_in[0];
    const float* Wih1  = (const float*)d_in[1];
    const float* Whh1  = (const float*)d_in[2];
    const float* bih1  = (const float*)d_in[3];
    const float* bhh1  = (const float*)d_in[4];
    const float* Wih2  = (const float*)d_in[5];
    const float* Whh2  = (const float*)d_in[6];
    const float* bih2  = (const float*)d_in[7];
    const float* bhh2  = (const float*)d_in[8];
    const float* Wlin  = (const float*)d_in[9];
    const float* blin  = (const float*)d_in[10];
    float* out = (float*)d_out;

    (void)in_sizes; (void)n_in; (void)out_size;

    static_assert(sizeof(Smem) <= 232448, "smem over sm_103a opt-in limit");
    cudaFuncSetAttribute(lstm_persistent_kernel,
                         cudaFuncAttributeMaxDynamicSharedMemorySize,
                         (int)sizeof(Smem));
    lstm_persistent_kernel<<<NCTA, NTHR, sizeof(Smem)>>>(
        x, Wih1, Whh1, bih1, bhh1, Wih2, Whh2, bih2, bhh2, Wlin, blin, out);
}